// round 3
// baseline (speedup 1.0000x reference)
#include <cuda_runtime.h>
#include <math.h>

#define NT   8192   // tokens
#define ND   1024   // d_model
#define NE   7      // experts
#define NCAP 3072   // capacity
#define NH   4096   // d_ff

// ---------------- scratch (static __device__ globals; no allocs allowed) ----
__device__ int   g_cnt[8];
__device__ int   g_idx[NE * NCAP];          // slot -> token id
__device__ int   g_slot[NT * 2];            // (t,k) -> global slot row (e*CAP+pos) or -1
__device__ float g_wgt[NT * 2];             // (t,k) -> combine weight
__device__ float g_h[(long long)NE * NCAP * NH]; // gelu(x@W1)  (352 MB)
__device__ float g_y[(long long)NE * NCAP * ND]; // h@W2        (88 MB)

// ---------------------------------------------------------------- init -----
__global__ void init_kernel() {
    if (threadIdx.x < 8) g_cnt[threadIdx.x] = 0;
}

// -------------------------------------------------------------- router -----
// One warp per token: 7 dot products of length 1024, top-2, sigmoid weights,
// atomic slot assignment.
__global__ void router_kernel(const float* __restrict__ x,
                              const float* __restrict__ Wg) {
    int gw   = (blockIdx.x * blockDim.x + threadIdx.x) >> 5;
    int lane = threadIdx.x & 31;
    if (gw >= NT) return;
    const float* xr = x + (long long)gw * ND;

    float acc[NE];
#pragma unroll
    for (int e = 0; e < NE; e++) acc[e] = 0.f;
    for (int d = lane; d < ND; d += 32) {
        float xv = xr[d];
        const float* wr = Wg + d * NE;
#pragma unroll
        for (int e = 0; e < NE; e++) acc[e] += xv * wr[e];
    }
#pragma unroll
    for (int e = 0; e < NE; e++) {
#pragma unroll
        for (int off = 16; off; off >>= 1)
            acc[e] += __shfl_xor_sync(0xffffffffu, acc[e], off);
    }
    if (lane == 0) {
        // top-1 (ties -> lowest index, matching lax.top_k)
        int i0 = 0; float v0 = acc[0];
#pragma unroll
        for (int e = 1; e < NE; e++) if (acc[e] > v0) { v0 = acc[e]; i0 = e; }
        // top-2
        int i1 = -1; float v1 = -3.4e38f;
#pragma unroll
        for (int e = 0; e < NE; e++)
            if (e != i0 && acc[e] > v1) { v1 = acc[e]; i1 = e; }
        // softmax renormalized over top-2 == sigmoid(logit diff); Z cancels
        float w0 = 1.f / (1.f + expf(v1 - v0));
        float w1 = 1.f - w0;
        int b = gw * 2;
        g_wgt[b]     = w0;
        g_wgt[b + 1] = w1;
        int p0 = atomicAdd(&g_cnt[i0], 1);
        if (p0 < NCAP) { int s = i0 * NCAP + p0; g_idx[s] = gw; g_slot[b] = s; }
        else           g_slot[b] = -1;
        int p1 = atomicAdd(&g_cnt[i1], 1);
        if (p1 < NCAP) { int s = i1 * NCAP + p1; g_idx[s] = gw; g_slot[b + 1] = s; }
        else           g_slot[b + 1] = -1;
    }
}

// --------------------------------------------------------------- gelu ------
__device__ __forceinline__ float gelu_tanh(float v) {
    // JAX default approximate=True (tanh form)
    float c = 0.7978845608028654f * (v + 0.044715f * v * v * v);
    return 0.5f * v * (1.f + tanhf(c));
}

// ------------------------------------------------- GEMM1: h = gelu(Xg@W1) --
// 128x128 tile, BK=8, 256 threads, 8x8 micro-tile (4+4 split -> conflict-free
// smem reads). A rows gathered from x via g_idx; rows >= cnt are zero-filled
// and never stored.
__global__ __launch_bounds__(256)
void gemm1_kernel(const float* __restrict__ x, const float* __restrict__ W1) {
    __shared__ float As[8][128];
    __shared__ float Bs[8][128];

    int e   = blockIdx.z;
    int cnt = min(g_cnt[e], NCAP);
    int m0  = blockIdx.y * 128;
    if (m0 >= cnt) return;
    int n0  = blockIdx.x * 128;

    int tid  = threadIdx.x;
    int r    = tid >> 1;            // A-load row 0..127
    int half = (tid & 1) * 4;       // A-load k-offset {0,4}
    const float* aptr = nullptr;
    if (m0 + r < cnt)
        aptr = x + (long long)g_idx[e * NCAP + m0 + r] * ND + half;

    int kb = tid >> 5;              // B-load k row 0..7
    int nb = (tid & 31) * 4;        // B-load col
    const float* bptr = W1 + (long long)e * ND * NH + (long long)kb * NH + n0 + nb;

    int tx = tid & 15, ty = tid >> 4;
    float acc[8][8];
#pragma unroll
    for (int i = 0; i < 8; i++)
#pragma unroll
        for (int j = 0; j < 8; j++) acc[i][j] = 0.f;

    float4 av = make_float4(0.f, 0.f, 0.f, 0.f);
    if (aptr) av = *(const float4*)(aptr);
    float4 bv = *(const float4*)(bptr);

    for (int k0 = 0; k0 < ND; k0 += 8) {
        __syncthreads();
        As[half + 0][r] = av.x; As[half + 1][r] = av.y;
        As[half + 2][r] = av.z; As[half + 3][r] = av.w;
        *(float4*)&Bs[kb][nb] = bv;
        __syncthreads();

        int kn = k0 + 8;
        if (kn < ND) {                       // prefetch next tile
            if (aptr) av = *(const float4*)(aptr + kn);
            bv = *(const float4*)(bptr + (long long)kn * NH);
        }
#pragma unroll
        for (int kk = 0; kk < 8; kk++) {
            float ra[8], rb[8];
            *(float4*)(ra)     = *(const float4*)&As[kk][ty * 4];
            *(float4*)(ra + 4) = *(const float4*)&As[kk][64 + ty * 4];
            *(float4*)(rb)     = *(const float4*)&Bs[kk][tx * 4];
            *(float4*)(rb + 4) = *(const float4*)&Bs[kk][64 + tx * 4];
#pragma unroll
            for (int i = 0; i < 8; i++)
#pragma unroll
                for (int j = 0; j < 8; j++)
                    acc[i][j] += ra[i] * rb[j];
        }
    }

    long long rowbase = (long long)e * NCAP;
#pragma unroll
    for (int i = 0; i < 8; i++) {
        int m = m0 + ((i < 4) ? (ty * 4 + i) : (64 + ty * 4 + (i - 4)));
        if (m >= cnt) continue;
        float* hr = g_h + (rowbase + m) * NH + n0;
        float4 o0, o1;
        o0.x = gelu_tanh(acc[i][0]); o0.y = gelu_tanh(acc[i][1]);
        o0.z = gelu_tanh(acc[i][2]); o0.w = gelu_tanh(acc[i][3]);
        o1.x = gelu_tanh(acc[i][4]); o1.y = gelu_tanh(acc[i][5]);
        o1.z = gelu_tanh(acc[i][6]); o1.w = gelu_tanh(acc[i][7]);
        *(float4*)(hr + tx * 4)      = o0;
        *(float4*)(hr + 64 + tx * 4) = o1;
    }
}

// --------------------------------------------------- GEMM2: y = h @ W2 -----
__global__ __launch_bounds__(256)
void gemm2_kernel(const float* __restrict__ W2) {
    __shared__ float As[8][128];
    __shared__ float Bs[8][128];

    int e   = blockIdx.z;
    int cnt = min(g_cnt[e], NCAP);
    int m0  = blockIdx.y * 128;
    if (m0 >= cnt) return;
    int n0  = blockIdx.x * 128;

    int tid  = threadIdx.x;
    int r    = tid >> 1;
    int half = (tid & 1) * 4;
    const float* aptr = nullptr;
    if (m0 + r < cnt)
        aptr = g_h + (long long)(e * NCAP + m0 + r) * NH + half;

    int kb = tid >> 5;
    int nb = (tid & 31) * 4;
    const float* bptr = W2 + (long long)e * NH * ND + (long long)kb * ND + n0 + nb;

    int tx = tid & 15, ty = tid >> 4;
    float acc[8][8];
#pragma unroll
    for (int i = 0; i < 8; i++)
#pragma unroll
        for (int j = 0; j < 8; j++) acc[i][j] = 0.f;

    float4 av = make_float4(0.f, 0.f, 0.f, 0.f);
    if (aptr) av = *(const float4*)(aptr);
    float4 bv = *(const float4*)(bptr);

    for (int k0 = 0; k0 < NH; k0 += 8) {
        __syncthreads();
        As[half + 0][r] = av.x; As[half + 1][r] = av.y;
        As[half + 2][r] = av.z; As[half + 3][r] = av.w;
        *(float4*)&Bs[kb][nb] = bv;
        __syncthreads();

        int kn = k0 + 8;
        if (kn < NH) {
            if (aptr) av = *(const float4*)(aptr + kn);
            bv = *(const float4*)(bptr + (long long)kn * ND);
        }
#pragma unroll
        for (int kk = 0; kk < 8; kk++) {
            float ra[8], rb[8];
            *(float4*)(ra)     = *(const float4*)&As[kk][ty * 4];
            *(float4*)(ra + 4) = *(const float4*)&As[kk][64 + ty * 4];
            *(float4*)(rb)     = *(const float4*)&Bs[kk][tx * 4];
            *(float4*)(rb + 4) = *(const float4*)&Bs[kk][64 + tx * 4];
#pragma unroll
            for (int i = 0; i < 8; i++)
#pragma unroll
                for (int j = 0; j < 8; j++)
                    acc[i][j] += ra[i] * rb[j];
        }
    }

    long long rowbase = (long long)e * NCAP;
#pragma unroll
    for (int i = 0; i < 8; i++) {
        int m = m0 + ((i < 4) ? (ty * 4 + i) : (64 + ty * 4 + (i - 4)));
        if (m >= cnt) continue;
        float* yr = g_y + (rowbase + m) * ND + n0;
        *(float4*)(yr + tx * 4)      = make_float4(acc[i][0], acc[i][1], acc[i][2], acc[i][3]);
        *(float4*)(yr + 64 + tx * 4) = make_float4(acc[i][4], acc[i][5], acc[i][6], acc[i][7]);
    }
}

// -------------------------------------------------------------- combine ----
__global__ void combine_kernel(float* __restrict__ out) {
    int t = blockIdx.x;
    int d = threadIdx.x * 4;   // 256 threads x 4 floats = 1024
    int   s0 = g_slot[t * 2],     s1 = g_slot[t * 2 + 1];
    float w0 = g_wgt[t * 2],      w1 = g_wgt[t * 2 + 1];
    float4 acc = make_float4(0.f, 0.f, 0.f, 0.f);
    if (s0 >= 0) {
        float4 a = *(const float4*)(g_y + (long long)s0 * ND + d);
        acc.x += w0 * a.x; acc.y += w0 * a.y; acc.z += w0 * a.z; acc.w += w0 * a.w;
    }
    if (s1 >= 0) {
        float4 a = *(const float4*)(g_y + (long long)s1 * ND + d);
        acc.x += w1 * a.x; acc.y += w1 * a.y; acc.z += w1 * a.z; acc.w += w1 * a.w;
    }
    *(float4*)(out + (long long)t * ND + d) = acc;
}

// ---------------------------------------------------------------- launch ---
extern "C" void kernel_launch(void* const* d_in, const int* in_sizes, int n_in,
                              void* d_out, int out_size) {
    const float* x  = (const float*)d_in[0];   // [T, D]
    const float* Wg = (const float*)d_in[1];   // [D, E]
    const float* W1 = (const float*)d_in[2];   // [E, D, H]
    const float* W2 = (const float*)d_in[3];   // [E, H, D]
    float* out = (float*)d_out;                // [T, D]

    init_kernel<<<1, 32>>>();
    router_kernel<<<NT / 8, 256>>>(x, Wg);                      // 8 warps/block
    gemm1_kernel<<<dim3(NH / 128, NCAP / 128, NE), 256>>>(x, W1);
    gemm2_kernel<<<dim3(ND / 128, NCAP / 128, NE), 256>>>(W2);
    combine_kernel<<<NT, 256>>>(out);
}

// round 9
// speedup vs baseline: 1.7907x; 1.7907x over previous
#include <cuda_runtime.h>
#include <cuda_bf16.h>
#include <stdint.h>
#include <math.h>

#define NT   8192   // tokens
#define ND   1024   // d_model
#define NE   7      // experts
#define NCAP 3072   // capacity
#define NH   4096   // d_ff

// ---------------- scratch (static __device__ globals; no allocs allowed) ----
// NOTE: these are ONLY referenced from device code (never passed as kernel
// arguments from host — that was the round-7/8 bug).
__device__ __align__(16) int   g_cnt[8];
__device__ __align__(16) int   g_idx[NE * NCAP];
__device__ __align__(16) int   g_slot[NT * 2];
__device__ __align__(16) float g_wgt[NT * 2];
__device__ __align__(16) float g_y[(size_t)NE * NCAP * ND];
__device__ __align__(16) __nv_bfloat16 g_x_hi[(size_t)NT * ND];
__device__ __align__(16) __nv_bfloat16 g_x_lo[(size_t)NT * ND];
__device__ __align__(16) __nv_bfloat16 g_h_hi[(size_t)NE * NCAP * NH];
__device__ __align__(16) __nv_bfloat16 g_h_lo[(size_t)NE * NCAP * NH];
__device__ __align__(16) __nv_bfloat16 g_w1t_hi[(size_t)NE * NH * ND];  // [E, H, D]
__device__ __align__(16) __nv_bfloat16 g_w1t_lo[(size_t)NE * NH * ND];
__device__ __align__(16) __nv_bfloat16 g_w2t_hi[(size_t)NE * ND * NH];  // [E, D, H]
__device__ __align__(16) __nv_bfloat16 g_w2t_lo[(size_t)NE * ND * NH];

// ------------------------------------------------------ PTX helpers --------
__device__ __forceinline__ uint32_t smem_u32(const void* p) {
    uint32_t a;
    asm("{ .reg .u64 t; cvta.to.shared.u64 t, %1; cvt.u32.u64 %0, t; }"
        : "=r"(a) : "l"(p));
    return a;
}
__device__ __forceinline__ void ldm4(uint32_t* r, uint32_t addr) {
    asm volatile("ldmatrix.sync.aligned.m8n8.x4.shared.b16 {%0,%1,%2,%3}, [%4];"
        : "=r"(r[0]), "=r"(r[1]), "=r"(r[2]), "=r"(r[3]) : "r"(addr));
}
__device__ __forceinline__ void mma16816(float* c, const uint32_t* a,
                                         uint32_t b0, uint32_t b1) {
    asm volatile("mma.sync.aligned.m16n8k16.row.col.f32.bf16.bf16.f32 "
        "{%0,%1,%2,%3}, {%4,%5,%6,%7}, {%8,%9}, {%0,%1,%2,%3};"
        : "+f"(c[0]), "+f"(c[1]), "+f"(c[2]), "+f"(c[3])
        : "r"(a[0]), "r"(a[1]), "r"(a[2]), "r"(a[3]), "r"(b0), "r"(b1));
}

// ---------------------------------------------------------------- init -----
__global__ void init_kernel() {
    if (threadIdx.x < 8) g_cnt[threadIdx.x] = 0;
}

// -------------------------------------------------------------- router -----
__global__ void router_kernel(const float* __restrict__ x,
                              const float* __restrict__ Wg) {
    int gw   = (blockIdx.x * blockDim.x + threadIdx.x) >> 5;
    int lane = threadIdx.x & 31;
    if (gw >= NT) return;
    const float* xr = x + (size_t)gw * ND;

    float acc[NE];
#pragma unroll
    for (int e = 0; e < NE; e++) acc[e] = 0.f;
    for (int d = lane; d < ND; d += 32) {
        float xv = xr[d];
        const float* wr = Wg + d * NE;
#pragma unroll
        for (int e = 0; e < NE; e++) acc[e] += xv * wr[e];
    }
#pragma unroll
    for (int e = 0; e < NE; e++) {
#pragma unroll
        for (int off = 16; off; off >>= 1)
            acc[e] += __shfl_xor_sync(0xffffffffu, acc[e], off);
    }
    if (lane == 0) {
        int i0 = 0; float v0 = acc[0];
#pragma unroll
        for (int e = 1; e < NE; e++) if (acc[e] > v0) { v0 = acc[e]; i0 = e; }
        int i1 = -1; float v1 = -3.4e38f;
#pragma unroll
        for (int e = 0; e < NE; e++)
            if (e != i0 && acc[e] > v1) { v1 = acc[e]; i1 = e; }
        float w0 = 1.f / (1.f + expf(v1 - v0));
        float w1 = 1.f - w0;
        int b = gw * 2;
        g_wgt[b]     = w0;
        g_wgt[b + 1] = w1;
        int p0 = atomicAdd(&g_cnt[i0], 1);
        if (p0 < NCAP) { int s = i0 * NCAP + p0; g_idx[s] = gw; g_slot[b] = s; }
        else           g_slot[b] = -1;
        int p1 = atomicAdd(&g_cnt[i1], 1);
        if (p1 < NCAP) { int s = i1 * NCAP + p1; g_idx[s] = gw; g_slot[b + 1] = s; }
        else           g_slot[b + 1] = -1;
    }
}

// ------------------------------------------------------------- split x -----
__global__ void split_x_kernel(const float* __restrict__ x) {
    size_t i = ((size_t)blockIdx.x * blockDim.x + threadIdx.x) * 4;
    float4 v = *(const float4*)(x + i);
    __nv_bfloat162 h0 = __floats2bfloat162_rn(v.x, v.y);
    __nv_bfloat162 h1 = __floats2bfloat162_rn(v.z, v.w);
    __nv_bfloat162 l0 = __floats2bfloat162_rn(v.x - __bfloat162float(h0.x),
                                              v.y - __bfloat162float(h0.y));
    __nv_bfloat162 l1 = __floats2bfloat162_rn(v.z - __bfloat162float(h1.x),
                                              v.w - __bfloat162float(h1.y));
    *(__nv_bfloat162*)(g_x_hi + i)     = h0;
    *(__nv_bfloat162*)(g_x_hi + i + 2) = h1;
    *(__nv_bfloat162*)(g_x_lo + i)     = l0;
    *(__nv_bfloat162*)(g_x_lo + i + 2) = l1;
}

// -------------------------------------------- weight transpose + bf16 split
// WSEL=1: W1 [E, ND, NH] -> g_w1t (R=ND, C=NH); WSEL=2: W2 -> g_w2t.
template<int WSEL>
__global__ void split_tr_kernel(const float* __restrict__ src) {
    constexpr int R = (WSEL == 1) ? ND : NH;
    constexpr int C = (WSEL == 1) ? NH : ND;
    __nv_bfloat16* hi = (WSEL == 1) ? g_w1t_hi : g_w2t_hi;
    __nv_bfloat16* lo = (WSEL == 1) ? g_w1t_lo : g_w2t_lo;

    __shared__ float t[32][33];
    int e  = blockIdx.z;
    int c0 = blockIdx.x * 32;
    int r0 = blockIdx.y * 32;
    int tx = threadIdx.x, ty = threadIdx.y;
    const float* S = src + (size_t)e * R * C;
    size_t dbase   = (size_t)e * R * C;
#pragma unroll
    for (int i = ty; i < 32; i += 8)
        t[i][tx] = S[(size_t)(r0 + i) * C + c0 + tx];
    __syncthreads();
#pragma unroll
    for (int i = ty; i < 32; i += 8) {
        float v = t[tx][i];
        __nv_bfloat16 h = __float2bfloat16(v);
        __nv_bfloat16 l = __float2bfloat16(v - __bfloat162float(h));
        size_t o = dbase + (size_t)(c0 + i) * R + r0 + tx;
        hi[o] = h; lo[o] = l;
    }
}

// --------------------------------------------------------------- gelu ------
__device__ __forceinline__ float gelu_tanh(float v) {
    float c = 0.7978845608028654f * (v + 0.044715f * v * v * v);
    return 0.5f * v * (1.f + tanhf(c));
}

// ----------------------------- bf16x3 grouped GEMM on mma.sync (HMMA) ------
// PHASE=1: h(split bf16) = gelu(gather(x) @ W1t), K=ND, N=NH
// PHASE=2: y(fp32)       = h @ W2t,               K=NH, N=ND
// CTA 128(M) x 128(N), BK=16 fp32-units/chunk, static SMEM, padded 80B rows
// (20 banks -> the 8-row ldmatrix footprint covers all 32 banks once).
// 3 MMA passes per k16: Ahi*Bhi + Ahi*Blo + Alo*Bhi -> fp32 accum.
#define ROWB 80

template<int PHASE>
__global__ __launch_bounds__(256)
void moe_mma_kernel() {
    constexpr int KTOT = (PHASE == 1) ? ND : NH;
    constexpr int NTOT = (PHASE == 1) ? NH : ND;
    const __nv_bfloat16* __restrict__ Ahi = (PHASE == 1) ? g_x_hi : g_h_hi;
    const __nv_bfloat16* __restrict__ Alo = (PHASE == 1) ? g_x_lo : g_h_lo;
    const __nv_bfloat16* __restrict__ Bhi = (PHASE == 1) ? g_w1t_hi : g_w2t_hi;
    const __nv_bfloat16* __restrict__ Blo = (PHASE == 1) ? g_w1t_lo : g_w2t_lo;

    __shared__ __align__(128) char sA[128 * ROWB];
    __shared__ __align__(128) char sB[128 * ROWB];

    const int tid  = threadIdx.x;
    const int wid  = tid >> 5;
    const int lane = tid & 31;

    const int e   = blockIdx.z;
    const int cnt = min(g_cnt[e], NCAP);
    const int m0  = blockIdx.y * 128;
    if (m0 >= cnt) return;
    const int n0  = blockIdx.x * 128;

    const uint32_t sAu = smem_u32(sA);
    const uint32_t sBu = smem_u32(sB);

    // ---- loader mapping: rr = row 0..127, half = which 8-elem k-half ----
    const int rr   = tid >> 1;
    const int half = tid & 1;

    const __nv_bfloat16 *arh, *arl;
    if (PHASE == 1) {
        int tok = (m0 + rr < cnt) ? g_idx[e * NCAP + m0 + rr] : 0;
        arh = Ahi + (size_t)tok * KTOT;
        arl = Alo + (size_t)tok * KTOT;
    } else {
        size_t ri = (size_t)(e * NCAP + m0 + rr) * KTOT;
        arh = Ahi + ri; arl = Alo + ri;
    }
    size_t bi = (size_t)(e * NTOT + n0 + rr) * KTOT;
    const __nv_bfloat16 *brh = Bhi + bi;
    const __nv_bfloat16 *brl = Blo + bi;

    const uint32_t st_hi = (uint32_t)rr * ROWB + half * 16;
    const uint32_t st_lo = st_hi + 32;

    constexpr int NCH = KTOT / 16;

    // prefetch chunk 0 into registers
    uint4 rah, ral, rbh, rbl;
    {
        int ko = half * 8;
        rah = *(const uint4*)(arh + ko);
        ral = *(const uint4*)(arl + ko);
        rbh = *(const uint4*)(brh + ko);
        rbl = *(const uint4*)(brl + ko);
    }

    const int wm = wid & 1;          // 2 M-warps (64 rows each)
    const int wn = wid >> 1;         // 4 N-warps (32 cols each)
    const int lr = lane & 15;
    const int lc = (lane >> 4) << 3; // 0 or 8 (k offset for ldmatrix tiles)
    const int gid = lane >> 2, tg = lane & 3;

    float acc[4][4][4];
#pragma unroll
    for (int mt = 0; mt < 4; mt++)
#pragma unroll
        for (int nt = 0; nt < 4; nt++)
#pragma unroll
            for (int q = 0; q < 4; q++) acc[mt][nt][q] = 0.f;

    for (int ch = 0; ch < NCH; ch++) {
        __syncthreads();                 // previous compute done -> store safe
        *(uint4*)(sA + st_hi) = rah;
        *(uint4*)(sA + st_lo) = ral;
        *(uint4*)(sB + st_hi) = rbh;
        *(uint4*)(sB + st_lo) = rbl;
        __syncthreads();                 // tile visible

        if (ch + 1 < NCH) {              // prefetch next chunk (hides DRAM)
            int ko = (ch + 1) * 16 + half * 8;
            rah = *(const uint4*)(arh + ko);
            ral = *(const uint4*)(arl + ko);
            rbh = *(const uint4*)(brh + ko);
            rbl = *(const uint4*)(brl + ko);
        }

        uint32_t ahi[4][4], alo[4][4], bhi[2][4], blo[2][4];
#pragma unroll
        for (int mt = 0; mt < 4; mt++) {
            uint32_t base = sAu + (uint32_t)(wm * 64 + mt * 16 + lr) * ROWB;
            ldm4(ahi[mt], base + lc * 2);
            ldm4(alo[mt], base + 32 + lc * 2);
        }
#pragma unroll
        for (int np = 0; np < 2; np++) {
            uint32_t base = sBu + (uint32_t)(wn * 32 + np * 16 + lr) * ROWB;
            ldm4(bhi[np], base + lc * 2);
            ldm4(blo[np], base + 32 + lc * 2);
        }
#pragma unroll
        for (int mt = 0; mt < 4; mt++)
#pragma unroll
            for (int nt = 0; nt < 4; nt++) {
                const int np = nt >> 1, s = nt & 1;
                mma16816(acc[mt][nt], ahi[mt], bhi[np][s], bhi[np][s + 2]);
                mma16816(acc[mt][nt], ahi[mt], blo[np][s], blo[np][s + 2]);
                mma16816(acc[mt][nt], alo[mt], bhi[np][s], bhi[np][s + 2]);
            }
    }

    // -------- epilogue --------
#pragma unroll
    for (int mt = 0; mt < 4; mt++) {
#pragma unroll
        for (int nt = 0; nt < 4; nt++) {
            int row = m0 + wm * 64 + mt * 16 + gid;
            int col = n0 + wn * 32 + nt * 8 + tg * 2;
#pragma unroll
            for (int hrow = 0; hrow < 2; hrow++) {
                int rcur = row + hrow * 8;
                if (rcur >= cnt) continue;
                float v0 = acc[mt][nt][hrow * 2];
                float v1 = acc[mt][nt][hrow * 2 + 1];
                size_t o = (size_t)(e * NCAP + rcur) * NTOT + col;
                if (PHASE == 1) {
                    v0 = gelu_tanh(v0); v1 = gelu_tanh(v1);
                    __nv_bfloat162 h = __floats2bfloat162_rn(v0, v1);
                    __nv_bfloat162 l = __floats2bfloat162_rn(
                        v0 - __bfloat162float(h.x), v1 - __bfloat162float(h.y));
                    *(__nv_bfloat162*)(g_h_hi + o) = h;
                    *(__nv_bfloat162*)(g_h_lo + o) = l;
                } else {
                    *(float2*)(g_y + o) = make_float2(v0, v1);
                }
            }
        }
    }
}

// -------------------------------------------------------------- combine ----
__global__ void combine_kernel(float* __restrict__ out) {
    int t = blockIdx.x;
    int d = threadIdx.x * 4;
    int   s0 = g_slot[t * 2],     s1 = g_slot[t * 2 + 1];
    float w0 = g_wgt[t * 2],      w1 = g_wgt[t * 2 + 1];
    float4 acc = make_float4(0.f, 0.f, 0.f, 0.f);
    if (s0 >= 0) {
        float4 a = *(const float4*)(g_y + (size_t)s0 * ND + d);
        acc.x += w0 * a.x; acc.y += w0 * a.y; acc.z += w0 * a.z; acc.w += w0 * a.w;
    }
    if (s1 >= 0) {
        float4 a = *(const float4*)(g_y + (size_t)s1 * ND + d);
        acc.x += w1 * a.x; acc.y += w1 * a.y; acc.z += w1 * a.z; acc.w += w1 * a.w;
    }
    *(float4*)(out + (size_t)t * ND + d) = acc;
}

// ---------------------------------------------------------------- launch ---
extern "C" void kernel_launch(void* const* d_in, const int* in_sizes, int n_in,
                              void* d_out, int out_size) {
    const float* x  = (const float*)d_in[0];   // [T, D]
    const float* Wg = (const float*)d_in[1];   // [D, E]
    const float* W1 = (const float*)d_in[2];   // [E, D, H]
    const float* W2 = (const float*)d_in[3];   // [E, H, D]
    float* out = (float*)d_out;                // [T, D]

    init_kernel<<<1, 32>>>();
    router_kernel<<<NT / 8, 256>>>(x, Wg);
    split_x_kernel<<<(NT * ND) / 1024, 256>>>(x);
    split_tr_kernel<1><<<dim3(NH / 32, ND / 32, NE), dim3(32, 8)>>>(W1);
    split_tr_kernel<2><<<dim3(ND / 32, NH / 32, NE), dim3(32, 8)>>>(W2);
    // GEMM1: h(split bf16) = gelu(Xg @ W1t)
    moe_mma_kernel<1><<<dim3(NH / 128, NCAP / 128, NE), 256>>>();
    // GEMM2: y(fp32) = h @ W2t
    moe_mma_kernel<2><<<dim3(ND / 128, NCAP / 128, NE), 256>>>();
    combine_kernel<<<NT, 256>>>(out);
}